// round 2
// baseline (speedup 1.0000x reference)
#include <cuda_runtime.h>
#include <cstdint>

#define NF    16
#define NB    32768
#define NE    64
#define NO    64
#define NH    128
#define NHASH 200000
#define TILE_B 128

// Shared-memory layout (float offsets). AsT/W1s region is UNION-reused for Hs.
//   AsT : [64][132]   emb tile, transposed (e-major)        floats [0, 8448)
//   W1s : [64][128]   fc1 weights (e-major, n contiguous)   floats [8448, 16640)
//   Hs  : [128][132]  relu(h) tile, k-major (m contiguous)  floats [0, 16896)  (overlaps AsT+W1s)
//   W2s : [128][64]   fc2 weights (k-major, o contiguous)   floats [16896, 25088)
//   b1s : [128]                                             floats [25088, 25216)
//   b2s : [64]                                              floats [25216, 25280)
#define AS_STRIDE 132
#define OFF_AST  0
#define OFF_W1S  8448
#define OFF_HS   0
#define OFF_W2S  16896
#define OFF_B1S  25088
#define OFF_B2S  25216
#define SMEM_FLOATS 25280
#define SMEM_BYTES  (SMEM_FLOATS * 4)

// Runtime detection of index dtype: JAX without x64 returns int32 even when
// int64 was requested. If the buffer is int64 (little-endian, values < 2^31),
// every odd int32 word (high half) is 0. With int32 random values in [0,1e6),
// P(first 64 odd words all zero) ~ 0.
__device__ int g_idx_is64;

__global__ void detect_idx_kernel(const int* __restrict__ raw) {
    int any = 0;
#pragma unroll
    for (int i = 0; i < 64; i++) any |= raw[2 * i + 1];
    g_idx_is64 = (any == 0) ? 1 : 0;
}

__global__ __launch_bounds__(256) void sparse_mlp_kernel(
    const int*   __restrict__ inputs_raw,   // int32 view of inputs [B][F] (int32 or int64)
    const float* __restrict__ tables,       // [F][HASH][E]
    const float* __restrict__ W1,           // [F][E][HID]
    const float* __restrict__ b1,           // [F][HID]
    const float* __restrict__ W2,           // [F][HID][O]
    const float* __restrict__ b2,           // [F][O]
    float*       __restrict__ out)          // [F][B][O]
{
    extern __shared__ float smem[];
    float* AsT = smem + OFF_AST;
    float* W1s = smem + OFF_W1S;
    float* Hs  = smem + OFF_HS;
    float* W2s = smem + OFF_W2S;
    float* b1s = smem + OFF_B1S;
    float* b2s = smem + OFF_B2S;

    const int f    = blockIdx.y;
    const int row0 = blockIdx.x * TILE_B;
    const int tid  = threadIdx.x;
    const int is64 = g_idx_is64;

    // ---------------- Phase 0: cooperative loads ----------------
    // W1 tile: global layout W1[f][e][n] == W1s[e][n] directly. 8192 floats.
    {
        const float4* src = (const float4*)(W1 + (size_t)f * NE * NH);
        float4* dst = (float4*)W1s;
#pragma unroll
        for (int i = 0; i < (NE * NH / 4) / 256; i++)
            dst[tid + i * 256] = src[tid + i * 256];
    }
    // W2 tile: W2[f][k][o] == W2s[k][o]. 8192 floats.
    {
        const float4* src = (const float4*)(W2 + (size_t)f * NH * NO);
        float4* dst = (float4*)W2s;
#pragma unroll
        for (int i = 0; i < (NH * NO / 4) / 256; i++)
            dst[tid + i * 256] = src[tid + i * 256];
    }
    if (tid < NH) b1s[tid] = b1[f * NH + tid];
    if (tid < NO) b2s[tid] = b2[f * NO + tid];

    // Embedding gather: 2 threads per row, each loads 32 floats (8 x float4),
    // stores transposed into AsT[e][m].
    {
        const int m  = tid >> 1;
        const int hf = tid & 1;
        const int gb = row0 + m;
        const int flat = gb * NF + f;
        const int v = is64 ? inputs_raw[2 * flat] : inputs_raw[flat];
        const int hidx = (v + 1) % NHASH;
        const float4* src =
            (const float4*)(tables + ((size_t)f * NHASH + hidx) * NE + hf * 32);
#pragma unroll
        for (int i = 0; i < 8; i++) {
            float4 val = src[i];
            const int e = hf * 32 + i * 4;
            AsT[(e + 0) * AS_STRIDE + m] = val.x;
            AsT[(e + 1) * AS_STRIDE + m] = val.y;
            AsT[(e + 2) * AS_STRIDE + m] = val.z;
            AsT[(e + 3) * AS_STRIDE + m] = val.w;
        }
    }
    __syncthreads();

    // ---------------- Phase 1: h = emb @ W1  (128m x 128n x 64k) ----------------
    // Thread grid 16(ty,m) x 16(tx,n), 8x8 microtile per thread.
    const int tx = tid & 15;
    const int ty = tid >> 4;

    float acc[64];
#pragma unroll
    for (int i = 0; i < 64; i++) acc[i] = 0.0f;

#pragma unroll 8
    for (int e = 0; e < NE; e++) {
        float4 a0 = *(const float4*)(AsT + e * AS_STRIDE + ty * 8);
        float4 a1 = *(const float4*)(AsT + e * AS_STRIDE + ty * 8 + 4);
        float4 w0 = *(const float4*)(W1s + e * NH + tx * 8);
        float4 w1 = *(const float4*)(W1s + e * NH + tx * 8 + 4);
        float av[8] = {a0.x, a0.y, a0.z, a0.w, a1.x, a1.y, a1.z, a1.w};
        float wv[8] = {w0.x, w0.y, w0.z, w0.w, w1.x, w1.y, w1.z, w1.w};
#pragma unroll
        for (int i = 0; i < 8; i++)
#pragma unroll
            for (int j = 0; j < 8; j++)
                acc[i * 8 + j] = fmaf(av[i], wv[j], acc[i * 8 + j]);
    }

    __syncthreads();  // everyone done reading AsT/W1s before Hs overwrite

    // ReLU + bias, store h transposed into Hs[n][m] (m contiguous).
#pragma unroll
    for (int j = 0; j < 8; j++) {
        const int n = tx * 8 + j;
        const float bias = b1s[n];
        float4 v0, v1;
        v0.x = fmaxf(acc[0 * 8 + j] + bias, 0.0f);
        v0.y = fmaxf(acc[1 * 8 + j] + bias, 0.0f);
        v0.z = fmaxf(acc[2 * 8 + j] + bias, 0.0f);
        v0.w = fmaxf(acc[3 * 8 + j] + bias, 0.0f);
        v1.x = fmaxf(acc[4 * 8 + j] + bias, 0.0f);
        v1.y = fmaxf(acc[5 * 8 + j] + bias, 0.0f);
        v1.z = fmaxf(acc[6 * 8 + j] + bias, 0.0f);
        v1.w = fmaxf(acc[7 * 8 + j] + bias, 0.0f);
        *(float4*)(Hs + n * AS_STRIDE + ty * 8)     = v0;
        *(float4*)(Hs + n * AS_STRIDE + ty * 8 + 4) = v1;
    }
    __syncthreads();

    // ---------------- Phase 2: out = h @ W2  (128m x 64o x 128k) ----------------
    // Thread grid 32(o2) x 8(my); microtile 16m x 2o per thread.
    const int o2 = tid & 31;
    const int my = tid >> 5;
    const int mbase = my * 16;

    float acc2[32];
#pragma unroll
    for (int i = 0; i < 32; i++) acc2[i] = 0.0f;

#pragma unroll 8
    for (int k = 0; k < NH; k++) {
        float4 h0 = *(const float4*)(Hs + k * AS_STRIDE + mbase);
        float4 h1 = *(const float4*)(Hs + k * AS_STRIDE + mbase + 4);
        float4 h2 = *(const float4*)(Hs + k * AS_STRIDE + mbase + 8);
        float4 h3 = *(const float4*)(Hs + k * AS_STRIDE + mbase + 12);
        float2 w  = *(const float2*)(W2s + k * NO + o2 * 2);
        float hv[16] = {h0.x, h0.y, h0.z, h0.w, h1.x, h1.y, h1.z, h1.w,
                        h2.x, h2.y, h2.z, h2.w, h3.x, h3.y, h3.z, h3.w};
#pragma unroll
        for (int i = 0; i < 16; i++) {
            acc2[i * 2 + 0] = fmaf(hv[i], w.x, acc2[i * 2 + 0]);
            acc2[i * 2 + 1] = fmaf(hv[i], w.y, acc2[i * 2 + 1]);
        }
    }

    // Epilogue: + b2, coalesced float2 stores. out[f][row0+m][o]
    {
        float2 bb;
        bb.x = b2s[o2 * 2];
        bb.y = b2s[o2 * 2 + 1];
        float* obase = out + ((size_t)f * NB + row0 + mbase) * NO + o2 * 2;
#pragma unroll
        for (int i = 0; i < 16; i++) {
            float2 r;
            r.x = acc2[i * 2 + 0] + bb.x;
            r.y = acc2[i * 2 + 1] + bb.y;
            *(float2*)(obase + (size_t)i * NO) = r;
        }
    }
}

extern "C" void kernel_launch(void* const* d_in, const int* in_sizes, int n_in,
                              void* d_out, int out_size) {
    const int*   inputs_raw = (const int*)d_in[0];
    const float* tables     = (const float*)d_in[1];
    const float* W1         = (const float*)d_in[2];
    const float* b1         = (const float*)d_in[3];
    const float* W2         = (const float*)d_in[4];
    const float* b2         = (const float*)d_in[5];
    float*       out        = (float*)d_out;

    // Idempotent; legal during graph capture (not a stream-ordered API).
    cudaFuncSetAttribute(sparse_mlp_kernel,
                         cudaFuncAttributeMaxDynamicSharedMemorySize, SMEM_BYTES);

    detect_idx_kernel<<<1, 1>>>(inputs_raw);

    dim3 grid(NB / TILE_B, NF);
    sparse_mlp_kernel<<<grid, 256, SMEM_BYTES>>>(inputs_raw, tables, W1, b1, W2,
                                                 b2, out);
}

// round 4
// speedup vs baseline: 1.0806x; 1.0806x over previous
#include <cuda_runtime.h>
#include <cuda_fp16.h>
#include <cstdint>

#define NF    16
#define NB    32768
#define NE    64
#define NO    64
#define NH    128
#define NHASH 200000
#define TILE_B 128

// fp16 tile strides (elements): K + 8 padding -> conflict-free ldmatrix rows
#define STRIDE1 72      // K=64 tiles (A1, B1)
#define STRIDE2 136     // K=128 tiles (H, B2)
#define S1B (STRIDE1 * 2)   // 144 bytes
#define S2B (STRIDE2 * 2)   // 272 bytes

// byte offsets in dynamic smem
#define OFF_A1HI 0                      // 128 x 144 = 18432
#define OFF_A1LO 18432
#define OFF_B1HI 36864                  // 128 x 144 = 18432
#define OFF_B1LO 55296                  // end 73728
#define OFF_HHI  0                      // 128 x 272 = 34816 (aliases A1)
#define OFF_HLO  36864                  // aliases B1 (34816 <= 36864)
#define OFF_B2HI 73728                  // 64 x 272 = 17408
#define OFF_B2LO 91136                  // end 108544
#define SMEM_BYTES 108544

__device__ __forceinline__ uint32_t smem_u32(const void* p) {
    uint32_t a;
    asm("{ .reg .u64 t; cvta.to.shared.u64 t, %1; cvt.u32.u64 %0, t; }" : "=r"(a) : "l"(p));
    return a;
}

__device__ __forceinline__ void ldsm_x4(uint32_t* r, uint32_t addr) {
    asm volatile("ldmatrix.sync.aligned.m8n8.x4.shared.b16 {%0,%1,%2,%3}, [%4];"
                 : "=r"(r[0]), "=r"(r[1]), "=r"(r[2]), "=r"(r[3]) : "r"(addr));
}

__device__ __forceinline__ void mma16816(float* d, const uint32_t* a, const uint32_t* b) {
    asm volatile(
        "mma.sync.aligned.m16n8k16.row.col.f32.f16.f16.f32 "
        "{%0,%1,%2,%3}, {%4,%5,%6,%7}, {%8,%9}, {%0,%1,%2,%3};"
        : "+f"(d[0]), "+f"(d[1]), "+f"(d[2]), "+f"(d[3])
        : "r"(a[0]), "r"(a[1]), "r"(a[2]), "r"(a[3]), "r"(b[0]), "r"(b[1]));
}

__device__ __forceinline__ void split_h(float x, __half& hi, __half& lo) {
    hi = __float2half_rn(x);
    lo = __float2half_rn(x - __half2float(hi));
}

// ---------------- index dtype detection (int64 vs int32) ----------------
__device__ int g_idx_is64;
__global__ void detect_idx_kernel(const int* __restrict__ raw) {
    int any = 0;
#pragma unroll
    for (int i = 0; i < 64; i++) any |= raw[2 * i + 1];
    g_idx_is64 = (any == 0) ? 1 : 0;
}

// ---------------- main kernel ----------------
__global__ __launch_bounds__(256, 2) void sparse_hmma_kernel(
    const int*   __restrict__ inputs_raw,
    const float* __restrict__ tables,
    const float* __restrict__ W1,
    const float* __restrict__ b1,
    const float* __restrict__ W2,
    const float* __restrict__ b2,
    float*       __restrict__ out)
{
    extern __shared__ char smem[];
    __shared__ float b1s[NH];
    __shared__ float b2s[NO];

    const uint32_t smem_u = smem_u32(smem);
    const int tid  = threadIdx.x;
    const int wid  = tid >> 5;
    const int lane = tid & 31;
    const int f    = blockIdx.y;
    const int row0 = blockIdx.x * TILE_B;
    const int is64 = g_idx_is64;

    if (tid < NH) b1s[tid] = b1[f * NH + tid];
    if (tid < NO) b2s[tid] = b2[f * NO + tid];

    // ---- stage B1 = W1^T : [n=128][k=64] hi/lo ----
    {
        const float4* src = (const float4*)(W1 + (size_t)f * NE * NH);
#pragma unroll
        for (int i = 0; i < 8; i++) {
            const int idx4 = tid + i * 256;
            float4 v = src[idx4];
            const int flat = idx4 * 4;
            const int e = flat >> 7;       // k
            const int n = flat & 127;      // 4 consecutive rows
            float vv[4] = {v.x, v.y, v.z, v.w};
#pragma unroll
            for (int j = 0; j < 4; j++) {
                __half hi, lo;
                split_h(vv[j], hi, lo);
                *(__half*)(smem + OFF_B1HI + (n + j) * S1B + e * 2) = hi;
                *(__half*)(smem + OFF_B1LO + (n + j) * S1B + e * 2) = lo;
            }
        }
    }
    // ---- stage B2 = W2^T : [n=64][k=128] hi/lo ----
    {
        const float4* src = (const float4*)(W2 + (size_t)f * NH * NO);
#pragma unroll
        for (int i = 0; i < 8; i++) {
            const int idx4 = tid + i * 256;
            float4 v = src[idx4];
            const int flat = idx4 * 4;
            const int h_ = flat >> 6;      // k
            const int o_ = flat & 63;      // 4 consecutive rows
            float vv[4] = {v.x, v.y, v.z, v.w};
#pragma unroll
            for (int j = 0; j < 4; j++) {
                __half hi, lo;
                split_h(vv[j], hi, lo);
                *(__half*)(smem + OFF_B2HI + (o_ + j) * S2B + h_ * 2) = hi;
                *(__half*)(smem + OFF_B2LO + (o_ + j) * S2B + h_ * 2) = lo;
            }
        }
    }
    // ---- gather A1 = emb tile [m=128][k=64] hi/lo ----
    {
        const int m  = tid >> 1;
        const int hf = tid & 1;
        const int flat = (row0 + m) * NF + f;
        const int v = is64 ? inputs_raw[2 * flat] : inputs_raw[flat];
        const int hidx = (v + 1) % NHASH;
        const float4* src =
            (const float4*)(tables + ((size_t)f * NHASH + hidx) * NE + hf * 32);
#pragma unroll
        for (int i = 0; i < 8; i++) {
            float4 val = src[i];
            const int k = hf * 32 + i * 4;
            float vv[4] = {val.x, val.y, val.z, val.w};
            __half h0, l0, h1, l1, h2, l2, h3, l3;
            split_h(vv[0], h0, l0);
            split_h(vv[1], h1, l1);
            split_h(vv[2], h2, l2);
            split_h(vv[3], h3, l3);
            char* phi = smem + OFF_A1HI + m * S1B + k * 2;
            char* plo = smem + OFF_A1LO + m * S1B + k * 2;
            *(__half2*)(phi)     = __halves2half2(h0, h1);
            *(__half2*)(phi + 4) = __halves2half2(h2, h3);
            *(__half2*)(plo)     = __halves2half2(l0, l1);
            *(__half2*)(plo + 4) = __halves2half2(l2, l3);
        }
    }
    __syncthreads();

    // ---- GEMM1: D1[128m x 128n] = emb @ W1^T, 3-pass fp16 ----
    // warp tile: m in [32*(wid&3), +32), n in [64*(wid>>2), +64)
    const int mbase = (wid & 3) * 32;
    const int nbase1 = (wid >> 2) * 64;
    const uint32_t a_lane1 = (uint32_t)((lane & 15) * S1B + (lane >> 4) * 16);
    const uint32_t b_lane1 = (uint32_t)(((lane & 7) + ((lane >> 4) << 3)) * S1B +
                                        ((lane >> 3) & 1) * 16);

    float acc1[2][8][4];
#pragma unroll
    for (int i = 0; i < 2; i++)
#pragma unroll
        for (int j = 0; j < 8; j++)
#pragma unroll
            for (int q = 0; q < 4; q++) acc1[i][j][q] = 0.0f;

#pragma unroll
    for (int p = 0; p < 3; p++) {
        const uint32_t aoff = (p == 1) ? OFF_A1LO : OFF_A1HI;
        const uint32_t boff = (p == 2) ? OFF_B1LO : OFF_B1HI;
        const uint32_t abase = smem_u + aoff + mbase * S1B + a_lane1;
        const uint32_t bbase = smem_u + boff + nbase1 * S1B + b_lane1;
#pragma unroll
        for (int ks = 0; ks < 4; ks++) {
            uint32_t a0[4], a1[4];
            ldsm_x4(a0, abase + ks * 32);
            ldsm_x4(a1, abase + 16 * S1B + ks * 32);
            uint32_t bf[4][4];
#pragma unroll
            for (int q = 0; q < 4; q++)
                ldsm_x4(bf[q], bbase + q * 16 * S1B + ks * 32);
#pragma unroll
            for (int nt = 0; nt < 8; nt++) {
                const uint32_t* b = &bf[nt >> 1][(nt & 1) * 2];
                mma16816(acc1[0][nt], a0, b);
                mma16816(acc1[1][nt], a1, b);
            }
        }
    }

    __syncthreads();   // all warps done reading A1/B1 before H overwrites them

    // ---- epilogue1: H = relu(D1 + b1), hi/lo fp16 -> smem ----
#pragma unroll
    for (int mt = 0; mt < 2; mt++) {
#pragma unroll
        for (int nt = 0; nt < 8; nt++) {
            const int r0 = mbase + mt * 16 + (lane >> 2);
            const int c0 = nbase1 + nt * 8 + 2 * (lane & 3);
            const float* a = acc1[mt][nt];
            float v00 = fmaxf(a[0] + b1s[c0], 0.0f);
            float v01 = fmaxf(a[1] + b1s[c0 + 1], 0.0f);
            float v10 = fmaxf(a[2] + b1s[c0], 0.0f);
            float v11 = fmaxf(a[3] + b1s[c0 + 1], 0.0f);
            __half h00, l00, h01, l01, h10, l10, h11, l11;
            split_h(v00, h00, l00);
            split_h(v01, h01, l01);
            split_h(v10, h10, l10);
            split_h(v11, h11, l11);
            *(__half2*)(smem + OFF_HHI + r0 * S2B + c0 * 2) = __halves2half2(h00, h01);
            *(__half2*)(smem + OFF_HLO + r0 * S2B + c0 * 2) = __halves2half2(l00, l01);
            *(__half2*)(smem + OFF_HHI + (r0 + 8) * S2B + c0 * 2) = __halves2half2(h10, h11);
            *(__half2*)(smem + OFF_HLO + (r0 + 8) * S2B + c0 * 2) = __halves2half2(l10, l11);
        }
    }
    __syncthreads();

    // ---- GEMM2: D2[128m x 64n] = H @ W2^T, 3-pass fp16 ----
    // warp tile: m in [32*(wid&3), +32), n in [32*(wid>>2), +32)
    const int nbase2 = (wid >> 2) * 32;
    const uint32_t a_lane2 = (uint32_t)((lane & 15) * S2B + (lane >> 4) * 16);
    const uint32_t b_lane2 = (uint32_t)(((lane & 7) + ((lane >> 4) << 3)) * S2B +
                                        ((lane >> 3) & 1) * 16);

    float acc2[2][4][4];
#pragma unroll
    for (int i = 0; i < 2; i++)
#pragma unroll
        for (int j = 0; j < 4; j++)
#pragma unroll
            for (int q = 0; q < 4; q++) acc2[i][j][q] = 0.0f;

#pragma unroll
    for (int p = 0; p < 3; p++) {
        const uint32_t aoff = (p == 1) ? OFF_HLO : OFF_HHI;
        const uint32_t boff = (p == 2) ? OFF_B2LO : OFF_B2HI;
        const uint32_t abase = smem_u + aoff + mbase * S2B + a_lane2;
        const uint32_t bbase = smem_u + boff + nbase2 * S2B + b_lane2;
#pragma unroll
        for (int ks = 0; ks < 8; ks++) {
            uint32_t a0[4], a1[4];
            ldsm_x4(a0, abase + ks * 32);
            ldsm_x4(a1, abase + 16 * S2B + ks * 32);
            uint32_t bf[2][4];
#pragma unroll
            for (int q = 0; q < 2; q++)
                ldsm_x4(bf[q], bbase + q * 16 * S2B + ks * 32);
#pragma unroll
            for (int nt = 0; nt < 4; nt++) {
                const uint32_t* b = &bf[nt >> 1][(nt & 1) * 2];
                mma16816(acc2[0][nt], a0, b);
                mma16816(acc2[1][nt], a1, b);
            }
        }
    }

    // ---- epilogue2: out = D2 + b2 (float2 stores, 32B-sector aligned) ----
#pragma unroll
    for (int mt = 0; mt < 2; mt++) {
#pragma unroll
        for (int nt = 0; nt < 4; nt++) {
            const int gm = row0 + mbase + mt * 16 + (lane >> 2);
            const int o  = nbase2 + nt * 8 + 2 * (lane & 3);
            const float* a = acc2[mt][nt];
            float2 r0, r1;
            r0.x = a[0] + b2s[o];
            r0.y = a[1] + b2s[o + 1];
            r1.x = a[2] + b2s[o];
            r1.y = a[3] + b2s[o + 1];
            *(float2*)(out + ((size_t)f * NB + gm) * NO + o) = r0;
            *(float2*)(out + ((size_t)f * NB + gm + 8) * NO + o) = r1;
        }
    }
}

extern "C" void kernel_launch(void* const* d_in, const int* in_sizes, int n_in,
                              void* d_out, int out_size) {
    const int*   inputs_raw = (const int*)d_in[0];
    const float* tables     = (const float*)d_in[1];
    const float* W1         = (const float*)d_in[2];
    const float* b1         = (const float*)d_in[3];
    const float* W2         = (const float*)d_in[4];
    const float* b2         = (const float*)d_in[5];
    float*       out        = (float*)d_out;

    cudaFuncSetAttribute(sparse_hmma_kernel,
                         cudaFuncAttributeMaxDynamicSharedMemorySize, SMEM_BYTES);

    detect_idx_kernel<<<1, 1>>>(inputs_raw);

    dim3 grid(NB / TILE_B, NF);
    sparse_hmma_kernel<<<grid, 256, SMEM_BYTES>>>(inputs_raw, tables, W1, b1, W2,
                                                  b2, out);
}

// round 6
// speedup vs baseline: 2.5521x; 2.3617x over previous
#include <cuda_runtime.h>
#include <cuda_fp16.h>
#include <cstdint>

#define NF    16
#define NB    32768
#define NE    64
#define NO    64
#define NH    128
#define NHASH 200000
#define TILE_B 128

// fp16 tile strides (bytes): K halves + 8 pad -> conflict-free ldmatrix rows
#define S1B 144     // K=64 tiles (A1): 72 halves
#define S2B 272     // K=128 tiles (H): 136 halves

// dynamic smem byte offsets (H aliases A1 region)
#define OFF_A1HI 0              // 128 x 144 = 18432
#define OFF_A1LO 18432          // end 36864
#define OFF_HHI  0              // 128 x 272 = 34816
#define OFF_HLO  34816          // end 69632
#define SMEM_BYTES 69632

// Pre-split weight fragments in mma.m16n8k16 B-fragment lane layout.
// g_w1frag[((f*4 + ks)*16 + n8)*32 + lane] = {bhi0, bhi1, blo0, blo1}
//   word0: {W[k0][n], W[k0+1][n]}, word1: {W[k0+8][n], W[k0+9][n]}
//   n = n8*8 + (lane>>2), k0 = ks*16 + (lane&3)*2
__device__ __align__(16) uint4 g_w1frag[NF * 4 * 16 * 32];   // 512 KB
__device__ __align__(16) uint4 g_w2frag[NF * 8 * 8 * 32];    // 512 KB
__device__ int g_idx_is64;

__device__ __forceinline__ uint32_t smem_u32(const void* p) {
    uint32_t a;
    asm("{ .reg .u64 t; cvta.to.shared.u64 t, %1; cvt.u32.u64 %0, t; }" : "=r"(a) : "l"(p));
    return a;
}

__device__ __forceinline__ void ldsm_x4(uint32_t* r, uint32_t addr) {
    asm volatile("ldmatrix.sync.aligned.m8n8.x4.shared.b16 {%0,%1,%2,%3}, [%4];"
                 : "=r"(r[0]), "=r"(r[1]), "=r"(r[2]), "=r"(r[3]) : "r"(addr));
}

__device__ __forceinline__ void mma16816(float* d, const uint32_t* a, uint32_t b0, uint32_t b1) {
    asm volatile(
        "mma.sync.aligned.m16n8k16.row.col.f32.f16.f16.f32 "
        "{%0,%1,%2,%3}, {%4,%5,%6,%7}, {%8,%9}, {%0,%1,%2,%3};"
        : "+f"(d[0]), "+f"(d[1]), "+f"(d[2]), "+f"(d[3])
        : "r"(a[0]), "r"(a[1]), "r"(a[2]), "r"(a[3]), "r"(b0), "r"(b1));
}

__device__ __forceinline__ void split_h(float x, __half& hi, __half& lo) {
    hi = __float2half_rn(x);
    lo = __float2half_rn(x - __half2float(hi));
}

__device__ __forceinline__ uint32_t pack2(__half a, __half b) {
    __half2 p = __halves2half2(a, b);
    return *reinterpret_cast<uint32_t*>(&p);
}

// ---------------- prep: idx dtype detect + weight fragment build ----------------
__global__ void prep_kernel(const float* __restrict__ W1,
                            const float* __restrict__ W2,
                            const int*   __restrict__ raw) {
    int g = blockIdx.x * blockDim.x + threadIdx.x;
    if (g == 0) {
        int any = 0;
#pragma unroll
        for (int i = 0; i < 64; i++) any |= raw[2 * i + 1];
        g_idx_is64 = (any == 0) ? 1 : 0;
    }
    if (g < NF * 4 * 16 * 32) {
        const int l  = g & 31;
        const int n8 = (g >> 5) & 15;
        const int ks = (g >> 9) & 3;
        const int f  = g >> 11;
        const int n  = n8 * 8 + (l >> 2);
        const int k0 = ks * 16 + (l & 3) * 2;
        const float* Wf = W1 + (size_t)f * NE * NH;
        float v00 = Wf[(k0 + 0) * NH + n];
        float v01 = Wf[(k0 + 1) * NH + n];
        float v10 = Wf[(k0 + 8) * NH + n];
        float v11 = Wf[(k0 + 9) * NH + n];
        __half h00, l00, h01, l01, h10, l10, h11, l11;
        split_h(v00, h00, l00); split_h(v01, h01, l01);
        split_h(v10, h10, l10); split_h(v11, h11, l11);
        uint4 r;
        r.x = pack2(h00, h01); r.y = pack2(h10, h11);
        r.z = pack2(l00, l01); r.w = pack2(l10, l11);
        g_w1frag[g] = r;
    } else {
        g -= NF * 4 * 16 * 32;
        const int l  = g & 31;
        const int n8 = (g >> 5) & 7;
        const int ks = (g >> 8) & 7;
        const int f  = g >> 11;
        const int n  = n8 * 8 + (l >> 2);
        const int k0 = ks * 16 + (l & 3) * 2;
        const float* Wf = W2 + (size_t)f * NH * NO;
        float v00 = Wf[(k0 + 0) * NO + n];
        float v01 = Wf[(k0 + 1) * NO + n];
        float v10 = Wf[(k0 + 8) * NO + n];
        float v11 = Wf[(k0 + 9) * NO + n];
        __half h00, l00, h01, l01, h10, l10, h11, l11;
        split_h(v00, h00, l00); split_h(v01, h01, l01);
        split_h(v10, h10, l10); split_h(v11, h11, l11);
        uint4 r;
        r.x = pack2(h00, h01); r.y = pack2(h10, h11);
        r.z = pack2(l00, l01); r.w = pack2(l10, l11);
        g_w2frag[g] = r;
    }
}

// ---------------- main kernel ----------------
__global__ __launch_bounds__(256, 2) void sparse_hmma_kernel(
    const int*   __restrict__ inputs_raw,
    const float* __restrict__ tables,
    const float* __restrict__ b1,
    const float* __restrict__ b2,
    float*       __restrict__ out)
{
    extern __shared__ char smem[];
    __shared__ float b1s[NH];
    __shared__ float b2s[NO];

    const uint32_t smem_u = smem_u32(smem);
    const int tid  = threadIdx.x;
    const int wid  = tid >> 5;
    const int lane = tid & 31;
    const int f    = blockIdx.y;
    const int row0 = blockIdx.x * TILE_B;
    const int is64 = g_idx_is64;

    if (tid < NH) b1s[tid] = b1[f * NH + tid];
    if (tid < NO) b2s[tid] = b2[f * NO + tid];

    // ---- gather A1 = emb tile [m=128][k=64] hi/lo, 16B STS ----
    {
        const int m  = tid >> 1;
        const int hf = tid & 1;
        const int flat = (row0 + m) * NF + f;
        const int v = is64 ? inputs_raw[2 * flat] : inputs_raw[flat];
        const int hidx = (v + 1) % NHASH;
        const float4* src =
            (const float4*)(tables + ((size_t)f * NHASH + hidx) * NE + hf * 32);
#pragma unroll
        for (int i = 0; i < 4; i++) {
            float4 va = src[2 * i];
            float4 vb = src[2 * i + 1];
            const int k = hf * 32 + i * 8;
            float vv[8] = {va.x, va.y, va.z, va.w, vb.x, vb.y, vb.z, vb.w};
            __half hi[8], lo[8];
#pragma unroll
            for (int j = 0; j < 8; j++) split_h(vv[j], hi[j], lo[j]);
            uint4 rhi, rlo;
            rhi.x = pack2(hi[0], hi[1]); rhi.y = pack2(hi[2], hi[3]);
            rhi.z = pack2(hi[4], hi[5]); rhi.w = pack2(hi[6], hi[7]);
            rlo.x = pack2(lo[0], lo[1]); rlo.y = pack2(lo[2], lo[3]);
            rlo.z = pack2(lo[4], lo[5]); rlo.w = pack2(lo[6], lo[7]);
            *(uint4*)(smem + OFF_A1HI + m * S1B + k * 2) = rhi;
            *(uint4*)(smem + OFF_A1LO + m * S1B + k * 2) = rlo;
        }
    }
    __syncthreads();

    // ---- GEMM1: D1[128m x 128n] = emb @ W1^T, 3-pass fp16, B from global ----
    const int mbase = (wid & 3) * 32;
    const int nb8_1 = (wid >> 2) * 8;      // n8 base (8 n-tiles per warp)
    const uint32_t a_lane1 = (uint32_t)((lane & 15) * S1B + (lane >> 4) * 16);
    const uint32_t abhi1 = smem_u + OFF_A1HI + mbase * S1B + a_lane1;
    const uint32_t ablo1 = smem_u + OFF_A1LO + mbase * S1B + a_lane1;

    float acc1[2][8][4];
#pragma unroll
    for (int i = 0; i < 2; i++)
#pragma unroll
        for (int j = 0; j < 8; j++)
#pragma unroll
            for (int q = 0; q < 4; q++) acc1[i][j][q] = 0.0f;

#pragma unroll
    for (int ks = 0; ks < 4; ks++) {
        uint32_t ah0[4], ah1[4], al0[4], al1[4];
        ldsm_x4(ah0, abhi1 + ks * 32);
        ldsm_x4(ah1, abhi1 + 16 * S1B + ks * 32);
        ldsm_x4(al0, ablo1 + ks * 32);
        ldsm_x4(al1, ablo1 + 16 * S1B + ks * 32);
        const uint4* wp = g_w1frag + ((f * 4 + ks) * 16 + nb8_1) * 32 + lane;
#pragma unroll
        for (int nt = 0; nt < 8; nt++) {
            uint4 b = wp[nt * 32];
            mma16816(acc1[0][nt], ah0, b.x, b.y);
            mma16816(acc1[1][nt], ah1, b.x, b.y);
            mma16816(acc1[0][nt], al0, b.x, b.y);
            mma16816(acc1[1][nt], al1, b.x, b.y);
            mma16816(acc1[0][nt], ah0, b.z, b.w);
            mma16816(acc1[1][nt], ah1, b.z, b.w);
        }
    }

    __syncthreads();   // A1 reads done before H overwrites the region

    // ---- epilogue1: H = relu(D1 + b1), hi/lo fp16 -> smem ----
    const int nbase1 = nb8_1 * 8;
#pragma unroll
    for (int mt = 0; mt < 2; mt++) {
#pragma unroll
        for (int nt = 0; nt < 8; nt++) {
            const int r0 = mbase + mt * 16 + (lane >> 2);
            const int c0 = nbase1 + nt * 8 + 2 * (lane & 3);
            const float* a = acc1[mt][nt];
            float v00 = fmaxf(a[0] + b1s[c0], 0.0f);
            float v01 = fmaxf(a[1] + b1s[c0 + 1], 0.0f);
            float v10 = fmaxf(a[2] + b1s[c0], 0.0f);
            float v11 = fmaxf(a[3] + b1s[c0 + 1], 0.0f);
            __half h00, l00, h01, l01, h10, l10, h11, l11;
            split_h(v00, h00, l00); split_h(v01, h01, l01);
            split_h(v10, h10, l10); split_h(v11, h11, l11);
            *(uint32_t*)(smem + OFF_HHI + r0 * S2B + c0 * 2) = pack2(h00, h01);
            *(uint32_t*)(smem + OFF_HLO + r0 * S2B + c0 * 2) = pack2(l00, l01);
            *(uint32_t*)(smem + OFF_HHI + (r0 + 8) * S2B + c0 * 2) = pack2(h10, h11);
            *(uint32_t*)(smem + OFF_HLO + (r0 + 8) * S2B + c0 * 2) = pack2(l10, l11);
        }
    }
    __syncthreads();

    // ---- GEMM2: D2[128m x 64n] = H @ W2^T, 3-pass fp16, B from global ----
    const int nb8_2 = (wid >> 2) * 4;      // n8 base (4 n-tiles per warp)
    const uint32_t a_lane2 = (uint32_t)((lane & 15) * S2B + (lane >> 4) * 16);
    const uint32_t abhi2 = smem_u + OFF_HHI + mbase * S2B + a_lane2;
    const uint32_t ablo2 = smem_u + OFF_HLO + mbase * S2B + a_lane2;

    float acc2[2][4][4];
#pragma unroll
    for (int i = 0; i < 2; i++)
#pragma unroll
        for (int j = 0; j < 4; j++)
#pragma unroll
            for (int q = 0; q < 4; q++) acc2[i][j][q] = 0.0f;

#pragma unroll
    for (int ks = 0; ks < 8; ks++) {
        uint32_t ah0[4], ah1[4], al0[4], al1[4];
        ldsm_x4(ah0, abhi2 + ks * 32);
        ldsm_x4(ah1, abhi2 + 16 * S2B + ks * 32);
        ldsm_x4(al0, ablo2 + ks * 32);
        ldsm_x4(al1, ablo2 + 16 * S2B + ks * 32);
        const uint4* wp = g_w2frag + ((f * 8 + ks) * 8 + nb8_2) * 32 + lane;
#pragma unroll
        for (int nt = 0; nt < 4; nt++) {
            uint4 b = wp[nt * 32];
            mma16816(acc2[0][nt], ah0, b.x, b.y);
            mma16816(acc2[1][nt], ah1, b.x, b.y);
            mma16816(acc2[0][nt], al0, b.x, b.y);
            mma16816(acc2[1][nt], al1, b.x, b.y);
            mma16816(acc2[0][nt], ah0, b.z, b.w);
            mma16816(acc2[1][nt], ah1, b.z, b.w);
        }
    }

    // ---- epilogue2: out = D2 + b2 ----
    const int nbase2 = nb8_2 * 8;
#pragma unroll
    for (int mt = 0; mt < 2; mt++) {
#pragma unroll
        for (int nt = 0; nt < 4; nt++) {
            const int gm = row0 + mbase + mt * 16 + (lane >> 2);
            const int o  = nbase2 + nt * 8 + 2 * (lane & 3);
            const float* a = acc2[mt][nt];
            float2 r0, r1;
            r0.x = a[0] + b2s[o];
            r0.y = a[1] + b2s[o + 1];
            r1.x = a[2] + b2s[o];
            r1.y = a[3] + b2s[o + 1];
            *(float2*)(out + ((size_t)f * NB + gm) * NO + o) = r0;
            *(float2*)(out + ((size_t)f * NB + gm + 8) * NO + o) = r1;
        }
    }
}

extern "C" void kernel_launch(void* const* d_in, const int* in_sizes, int n_in,
                              void* d_out, int out_size) {
    const int*   inputs_raw = (const int*)d_in[0];
    const float* tables     = (const float*)d_in[1];
    const float* W1         = (const float*)d_in[2];
    const float* b1         = (const float*)d_in[3];
    const float* W2         = (const float*)d_in[4];
    const float* b2         = (const float*)d_in[5];
    float*       out        = (float*)d_out;

    cudaFuncSetAttribute(sparse_hmma_kernel,
                         cudaFuncAttributeMaxDynamicSharedMemorySize, SMEM_BYTES);

    prep_kernel<<<256, 256>>>(W1, W2, inputs_raw);

    dim3 grid(NB / TILE_B, NF);
    sparse_hmma_kernel<<<grid, 256, SMEM_BYTES>>>(inputs_raw, tables, b1, b2, out);
}